// round 2
// baseline (speedup 1.0000x reference)
#include <cuda_runtime.h>
#include <cstdint>

#define NUM_EXPERTS 8
#define HIDDEN 1024
#define INTER 4096
#define NTOK 2048
#define SOFTCAPV 30.0f
#define MAXROWS (NTOK * 2)

// ---------------- scratch (device globals; no allocs allowed) ----------------
__device__ int   g_counts[NUM_EXPERTS];
__device__ int   g_base[NUM_EXPERTS];
__device__ int   g_fill[NUM_EXPERTS];
__device__ int   g_row_token[MAXROWS];
__device__ float g_row_weight[MAXROWS];
__device__ int   g_tok_e[NTOK * 2];
__device__ float g_tok_w[NTOK * 2];
__device__ float g_scratch[(size_t)MAXROWS * INTER];   // 64 MB act buffer

// ---------------- small kernels ----------------
__global__ void k_zero_out(float* __restrict__ out) {
    int i = blockIdx.x * blockDim.x + threadIdx.x;
    ((float4*)out)[i] = make_float4(0.f, 0.f, 0.f, 0.f);
    if (blockIdx.x == 0 && threadIdx.x < NUM_EXPERTS) g_counts[threadIdx.x] = 0;
}

__global__ void k_router(const float* __restrict__ x, const float* __restrict__ wg) {
    int warp = (blockIdx.x * blockDim.x + threadIdx.x) >> 5;
    int lane = threadIdx.x & 31;
    if (warp >= NTOK) return;
    const float* xr = x + (size_t)warp * HIDDEN;
    float acc[NUM_EXPERTS];
#pragma unroll
    for (int e = 0; e < NUM_EXPERTS; e++) acc[e] = 0.f;
    for (int h = lane; h < HIDDEN; h += 32) {
        float xv = xr[h];
#pragma unroll
        for (int e = 0; e < NUM_EXPERTS; e++) acc[e] += xv * wg[e * HIDDEN + h];
    }
#pragma unroll
    for (int off = 16; off; off >>= 1)
#pragma unroll
        for (int e = 0; e < NUM_EXPERTS; e++)
            acc[e] += __shfl_xor_sync(0xffffffffu, acc[e], off);
    if (lane == 0) {
        float l[NUM_EXPERTS];
#pragma unroll
        for (int e = 0; e < NUM_EXPERTS; e++)
            l[e] = SOFTCAPV * tanhf(acc[e] / SOFTCAPV);
        // top-2 (earliest index wins ties, matching jax top_k)
        int b = 0; float vb = l[0];
#pragma unroll
        for (int e = 1; e < NUM_EXPERTS; e++) if (l[e] > vb) { b = e; vb = l[e]; }
        int s = -1; float vs = -1e30f;
#pragma unroll
        for (int e = 0; e < NUM_EXPERTS; e++)
            if (e != b && l[e] > vs) { s = e; vs = l[e]; }
        // softmax over full set then renormalize over top2 == 2-way softmax
        float wa = 1.f / (1.f + expf(vs - vb));
        g_tok_e[2 * warp]     = b;  g_tok_w[2 * warp]     = wa;
        g_tok_e[2 * warp + 1] = s;  g_tok_w[2 * warp + 1] = 1.f - wa;
        atomicAdd(&g_counts[b], 1);
        atomicAdd(&g_counts[s], 1);
    }
}

__global__ void k_offsets() {
    if (threadIdx.x == 0) {
        int acc = 0;
        for (int e = 0; e < NUM_EXPERTS; e++) { g_base[e] = acc; acc += g_counts[e]; }
    }
    if (threadIdx.x < NUM_EXPERTS) g_fill[threadIdx.x] = 0;
}

__global__ void k_scatter() {
    int t = blockIdx.x * blockDim.x + threadIdx.x;
    if (t >= NTOK) return;
#pragma unroll
    for (int k = 0; k < 2; k++) {
        int e = g_tok_e[2 * t + k];
        int p = atomicAdd(&g_fill[e], 1);
        int r = g_base[e] + p;
        g_row_token[r]  = t;
        g_row_weight[r] = g_tok_w[2 * t + k];
    }
}

// ---------------- tf32 mma GEMM ----------------
#define BM 128
#define BN 128
#define BK 16
#define BKP (BK + 4)

__device__ __forceinline__ uint32_t f2tf32(float f) {
    uint32_t u;
    asm("cvt.rna.tf32.f32 %0, %1;" : "=r"(u) : "f"(f));
    return u;
}

__device__ __forceinline__ void mma_tf32(float* c, const uint32_t* a, const uint32_t* b) {
    asm volatile(
        "mma.sync.aligned.m16n8k8.row.col.f32.tf32.tf32.f32 "
        "{%0,%1,%2,%3},{%4,%5,%6,%7},{%8,%9},{%0,%1,%2,%3};"
        : "+f"(c[0]), "+f"(c[1]), "+f"(c[2]), "+f"(c[3])
        : "r"(a[0]), "r"(a[1]), "r"(a[2]), "r"(a[3]), "r"(b[0]), "r"(b[1]));
}

__device__ __forceinline__ void cp_async16(uint32_t dst, const void* src, int src_sz) {
    asm volatile("cp.async.cg.shared.global [%0], [%1], 16, %2;\n"
                 :: "r"(dst), "l"(src), "r"(src_sz));
}

// MODE 0: h1 = gather(x) @ w1^T -> scratch
// MODE 1: h3 = gather(x) @ w3^T ; scratch = gelu(scratch) * h3
// MODE 2: C  = scratch @ w2^T ; out[token] += weight * C  (atomic)
template <int MODE, int KDIM, int NDIM>
__global__ void __launch_bounds__(256) k_gemm(const float* __restrict__ Asrc,
                                              const float* __restrict__ W,
                                              float* __restrict__ Out) {
    int e   = blockIdx.z;
    int cnt = g_counts[e];
    int m0  = blockIdx.y * BM;
    if (m0 >= cnt) return;
    int n0    = blockIdx.x * BN;
    int rbase = g_base[e];
    const float* Ap = (MODE == 2) ? (const float*)g_scratch : Asrc;
    const float* B  = W + (size_t)e * NDIM * KDIM;

    __shared__ __align__(16) float As[2][BM][BKP];
    __shared__ __align__(16) float Bs[2][BN][BKP];

    int tid = threadIdx.x;
    int lane = tid & 31, warp = tid >> 5;
    int wm = warp & 1, wn = warp >> 1;       // 2 x 4 warp grid, warp tile 64x32
    int g = lane >> 2, tg = lane & 3;

    // per-thread load descriptors: 2 (row,chunk) pairs per matrix per stage
    const float* aptr[2];
    const float* bptr[2];
    int asz[2];
#pragma unroll
    for (int p = 0; p < 2; p++) {
        int id = tid + p * 256;
        int row = id >> 2, ch = id & 3;
        int mrow = m0 + row;
        if (MODE == 2) {
            int r = rbase + (mrow < cnt ? mrow : 0);
            aptr[p] = Ap + (size_t)r * KDIM + ch * 4;
        } else {
            int t = (mrow < cnt) ? g_row_token[rbase + mrow] : 0;
            aptr[p] = Ap + (size_t)t * KDIM + ch * 4;
        }
        asz[p]  = (mrow < cnt) ? 16 : 0;
        bptr[p] = B + (size_t)(n0 + row) * KDIM + ch * 4;
    }

    float acc[4][4][4];
#pragma unroll
    for (int i = 0; i < 4; i++)
#pragma unroll
        for (int j = 0; j < 4; j++)
#pragma unroll
            for (int c = 0; c < 4; c++) acc[i][j][c] = 0.f;

    auto issue = [&](int st, int kt) {
        int k0 = kt * BK;
#pragma unroll
        for (int p = 0; p < 2; p++) {
            int id = tid + p * 256;
            int row = id >> 2, ch = id & 3;
            uint32_t da = (uint32_t)__cvta_generic_to_shared(&As[st][row][ch * 4]);
            cp_async16(da, aptr[p] + k0, asz[p]);
            uint32_t db = (uint32_t)__cvta_generic_to_shared(&Bs[st][row][ch * 4]);
            cp_async16(db, bptr[p] + k0, 16);
        }
        asm volatile("cp.async.commit_group;\n");
    };

    constexpr int KT = KDIM / BK;
    issue(0, 0);
    for (int kt = 0; kt < KT; ++kt) {
        int cur = kt & 1;
        if (kt + 1 < KT) {
            issue(cur ^ 1, kt + 1);
            asm volatile("cp.async.wait_group 1;\n");
        } else {
            asm volatile("cp.async.wait_group 0;\n");
        }
        __syncthreads();
#pragma unroll
        for (int kk = 0; kk < BK; kk += 8) {
            uint32_t a[4][4], b[4][2];
#pragma unroll
            for (int mt = 0; mt < 4; mt++) {
                int r = wm * 64 + mt * 16;
                a[mt][0] = f2tf32(As[cur][r + g][kk + tg]);
                a[mt][1] = f2tf32(As[cur][r + g + 8][kk + tg]);
                a[mt][2] = f2tf32(As[cur][r + g][kk + tg + 4]);
                a[mt][3] = f2tf32(As[cur][r + g + 8][kk + tg + 4]);
            }
#pragma unroll
            for (int nt = 0; nt < 4; nt++) {
                int c = wn * 32 + nt * 8;
                b[nt][0] = f2tf32(Bs[cur][c + g][kk + tg]);
                b[nt][1] = f2tf32(Bs[cur][c + g][kk + tg + 4]);
            }
#pragma unroll
            for (int mt = 0; mt < 4; mt++)
#pragma unroll
                for (int nt = 0; nt < 4; nt++)
                    mma_tf32(acc[mt][nt], a[mt], b[nt]);
        }
        __syncthreads();
    }

    // epilogue
#pragma unroll
    for (int mt = 0; mt < 4; mt++) {
#pragma unroll
        for (int nt = 0; nt < 4; nt++) {
#pragma unroll
            for (int cr = 0; cr < 4; cr++) {
                int row = wm * 64 + mt * 16 + g + ((cr >> 1) ? 8 : 0);
                int mg = m0 + row;
                if (mg >= cnt) continue;
                int col = n0 + wn * 32 + nt * 8 + tg * 2 + (cr & 1);
                float v = acc[mt][nt][cr];
                if (MODE == 0) {
                    g_scratch[(size_t)(rbase + mg) * INTER + col] = v;
                } else if (MODE == 1) {
                    size_t idx = (size_t)(rbase + mg) * INTER + col;
                    float h1 = g_scratch[idx];
                    float ge = 0.5f * h1 * (1.f + erff(h1 * 0.70710678118654752f));
                    g_scratch[idx] = ge * v;
                } else {
                    int t  = g_row_token[rbase + mg];
                    float w = g_row_weight[rbase + mg];
                    atomicAdd(&Out[(size_t)t * HIDDEN + col], w * v);
                }
            }
        }
    }
}

// ---------------- launch ----------------
extern "C" void kernel_launch(void* const* d_in, const int* in_sizes, int n_in,
                              void* d_out, int out_size) {
    const float* x  = (const float*)d_in[0];
    const float* wg = (const float*)d_in[1];
    const float* w1 = (const float*)d_in[2];
    const float* w3 = (const float*)d_in[3];
    const float* w2 = (const float*)d_in[4];
    float* out = (float*)d_out;

    k_zero_out<<<2048, 256>>>(out);            // 2048*256*4 = 2M floats
    k_router<<<256, 256>>>(x, wg);             // 2048 warps = 2048 tokens
    k_offsets<<<1, 32>>>();
    k_scatter<<<8, 256>>>();

    dim3 g13(INTER / BN, NTOK / BM, NUM_EXPERTS);   // 32 x 16 x 8
    k_gemm<0, HIDDEN, INTER><<<g13, 256>>>(x, w1, nullptr);
    k_gemm<1, HIDDEN, INTER><<<g13, 256>>>(x, w3, nullptr);
    dim3 g2(HIDDEN / BN, NTOK / BM, NUM_EXPERTS);   // 8 x 16 x 8
    k_gemm<2, INTER, HIDDEN><<<g2, 256>>>(nullptr, w2, out);
}